// round 14
// baseline (speedup 1.0000x reference)
#include <cuda_runtime.h>
#include <cuda_fp16.h>
#include <math.h>
#include <cstdint>

#define B_   8
#define H_   16
#define L_   512
#define DIM_ 1024
#define HD_  64
#define SEQN (B_ * L_ * DIM_)   // 4194304

// fp16 scratch (device globals: allocation-free per harness rules)
__device__ __align__(16) __half g_Wh [4 * 1024 * 1024];   // Wq,Wk,Wv,Wo
__device__ __align__(16) __half g_s1h[SEQN];
__device__ __align__(16) __half g_s2h[SEQN];
__device__ __align__(16) __half g_Qh [SEQN];
__device__ __align__(16) __half g_Kh [SEQN];
__device__ __align__(16) __half g_Vh [SEQN];
__device__ __align__(16) __half g_AOh[SEQN];

// persistent-kernel work counters (zeroed by cvt kernel each launch/replay)
__device__ int g_ctr_qkv;
__device__ int g_ctr_attn;

#define QKV_TILES  768    // 8 x 32 x 3
#define ATTN_TILES 1024   // 128 bh x 8 i-tiles
#define PERSIST_CTAS 296  // 2 per SM x 148

// ===========================================================================
// helpers
// ===========================================================================
__device__ __forceinline__ uint32_t pk(float lo, float hi) {
    uint32_t d;
    asm("cvt.rn.f16x2.f32 %0, %1, %2;" : "=r"(d) : "f"(hi), "f"(lo));
    return d;
}

__device__ __forceinline__ void mma_f16(
    float& d0, float& d1, float& d2, float& d3,
    uint32_t a0, uint32_t a1, uint32_t a2, uint32_t a3,
    uint32_t b0, uint32_t b1)
{
    asm volatile(
        "mma.sync.aligned.m16n8k16.row.col.f32.f16.f16.f32 "
        "{%0,%1,%2,%3}, {%4,%5,%6,%7}, {%8,%9}, {%0,%1,%2,%3};"
        : "+f"(d0), "+f"(d1), "+f"(d2), "+f"(d3)
        : "r"(a0), "r"(a1), "r"(a2), "r"(a3), "r"(b0), "r"(b1));
}

// ===========================================================================
// One-time fp32 -> fp16 conversion of inputs (z selects tensor).
// Also zeroes the persistent-work counters (runs before all consumers).
// ===========================================================================
__global__ __launch_bounds__(256) void cvt_f16_kernel(
    const float* __restrict__ s1, const float* __restrict__ s2,
    const float* __restrict__ wq, const float* __restrict__ wk,
    const float* __restrict__ wv, const float* __restrict__ wo)
{
    if (blockIdx.x == 0 && blockIdx.z == 0 && threadIdx.x == 0) {
        g_ctr_qkv = 0;
        g_ctr_attn = 0;
    }

    const int z = blockIdx.z;
    const float* src;
    __half* dst;
    int n4;
    if      (z == 0) { src = s1; dst = g_s1h;               n4 = SEQN / 4; }
    else if (z == 1) { src = s2; dst = g_s2h;               n4 = SEQN / 4; }
    else if (z == 2) { src = wq; dst = g_Wh;                n4 = 262144; }
    else if (z == 3) { src = wk; dst = g_Wh + 1048576;      n4 = 262144; }
    else if (z == 4) { src = wv; dst = g_Wh + 2 * 1048576;  n4 = 262144; }
    else             { src = wo; dst = g_Wh + 3 * 1048576;  n4 = 262144; }

    for (int i = blockIdx.x * blockDim.x + threadIdx.x; i < n4;
         i += gridDim.x * blockDim.x) {
        float4 v = __ldg((const float4*)src + i);
        uint2 o;
        o.x = pk(v.x, v.y);
        o.y = pk(v.z, v.w);
        *((uint2*)dst + i) = o;
    }
}

// ===========================================================================
// GEMM tile body (round-10/13 math, bit-identical):
// C[128,128] tile at (bx, by): A[by*128.., :] @ W[bx*128.., :]^T + bias
// 4 warps (2m x 2n), warp tile 64x64. KB=32, 2-stage, LDG reg prefetch.
// Writes fp16 to Ch if non-null, else fp32 to Cf.
// ===========================================================================
#define GK    1024
#define KB    32
#define NCH   (GK / KB)   // 32
#define SST   20

struct GemmSmem {
    uint32_t As[2][128 * SST];
    uint32_t Bs[2][128 * SST];
    float s_bias[128];
};

__device__ __forceinline__ void gemm_tile(
    GemmSmem& sm, int bx, int by,
    const __half* __restrict__ A, const __half* __restrict__ W,
    const float* __restrict__ bias,
    __half* __restrict__ Ch, float* __restrict__ Cf)
{
    const int tid  = threadIdx.x;
    const int wid  = tid >> 5;
    const int lane = tid & 31;
    const int g    = lane >> 2;
    const int tg   = lane & 3;
    const int mrow = (wid >> 1) * 64;
    const int ncol = (wid & 1) * 64;

    const __half* Arow = A + (size_t)by * 128 * GK;
    const __half* Wrow = W + (size_t)bx * 128 * GK;

    if (tid < 128) sm.s_bias[tid] = bias[bx * 128 + tid];

    int rL[4], qL[4];
#pragma unroll
    for (int t = 0; t < 4; t++) {
        const int s = tid + t * 128;
        rL[t] = s >> 2;
        qL[t] = s & 3;
    }

    float acc[4][8][4];
#pragma unroll
    for (int mt = 0; mt < 4; mt++)
#pragma unroll
        for (int nt = 0; nt < 8; nt++)
#pragma unroll
            for (int e = 0; e < 4; e++) acc[mt][nt][e] = 0.f;

#pragma unroll
    for (int t = 0; t < 4; t++) {
        uint4 a = *(const uint4*)(Arow + (size_t)rL[t] * GK + qL[t] * 8);
        uint4 b = *(const uint4*)(Wrow + (size_t)rL[t] * GK + qL[t] * 8);
        *(uint4*)&sm.As[0][rL[t] * SST + qL[t] * 4] = a;
        *(uint4*)&sm.Bs[0][rL[t] * SST + qL[t] * 4] = b;
    }
    __syncthreads();

    for (int i = 0; i < NCH; i++) {
        const int st = i & 1;
        uint4 va[4], vb[4];
        const bool more = (i + 1 < NCH);
        if (more) {
            const int ko = (i + 1) * KB;
#pragma unroll
            for (int t = 0; t < 4; t++) {
                va[t] = *(const uint4*)(Arow + (size_t)rL[t] * GK + ko + qL[t] * 8);
                vb[t] = *(const uint4*)(Wrow + (size_t)rL[t] * GK + ko + qL[t] * 8);
            }
        }

#pragma unroll
        for (int ks = 0; ks < 2; ks++) {
            uint32_t a[4][4];
#pragma unroll
            for (int mt = 0; mt < 4; mt++) {
                const int rb = mrow + mt * 16 + g;
                a[mt][0] = sm.As[st][(rb)     * SST + ks * 8 + tg];
                a[mt][1] = sm.As[st][(rb + 8) * SST + ks * 8 + tg];
                a[mt][2] = sm.As[st][(rb)     * SST + ks * 8 + tg + 4];
                a[mt][3] = sm.As[st][(rb + 8) * SST + ks * 8 + tg + 4];
            }
#pragma unroll
            for (int nt = 0; nt < 8; nt++) {
                const int rw = ncol + nt * 8 + g;
                uint32_t b0 = sm.Bs[st][rw * SST + ks * 8 + tg];
                uint32_t b1 = sm.Bs[st][rw * SST + ks * 8 + tg + 4];
#pragma unroll
                for (int mt = 0; mt < 4; mt++)
                    mma_f16(acc[mt][nt][0], acc[mt][nt][1], acc[mt][nt][2], acc[mt][nt][3],
                            a[mt][0], a[mt][1], a[mt][2], a[mt][3], b0, b1);
            }
        }

        if (more) {
            const int ns = st ^ 1;
#pragma unroll
            for (int t = 0; t < 4; t++) {
                *(uint4*)&sm.As[ns][rL[t] * SST + qL[t] * 4] = va[t];
                *(uint4*)&sm.Bs[ns][rL[t] * SST + qL[t] * 4] = vb[t];
            }
            __syncthreads();
        }
    }

    if (Ch) {
#pragma unroll
        for (int mt = 0; mt < 4; mt++) {
#pragma unroll
            for (int nt = 0; nt < 8; nt++) {
                const int row = mrow + mt * 16 + g;
                const int col = ncol + nt * 8 + 2 * tg;
                const int gm0 = by * 128 + row;
                const int gc  = bx * 128 + col;
                *(uint32_t*)(Ch + (size_t)gm0 * DIM_ + gc) =
                    pk(acc[mt][nt][0] + sm.s_bias[col], acc[mt][nt][1] + sm.s_bias[col + 1]);
                *(uint32_t*)(Ch + (size_t)(gm0 + 8) * DIM_ + gc) =
                    pk(acc[mt][nt][2] + sm.s_bias[col], acc[mt][nt][3] + sm.s_bias[col + 1]);
            }
        }
    } else {
#pragma unroll
        for (int mt = 0; mt < 4; mt++) {
#pragma unroll
            for (int nt = 0; nt < 8; nt++) {
                const int row = mrow + mt * 16 + g;
                const int col = ncol + nt * 8 + 2 * tg;
                const int gm0 = by * 128 + row;
                const int gc  = bx * 128 + col;
                float2 o;
                o.x = acc[mt][nt][0] + sm.s_bias[col];
                o.y = acc[mt][nt][1] + sm.s_bias[col + 1];
                *(float2*)(Cf + (size_t)gm0 * DIM_ + gc) = o;
                o.x = acc[mt][nt][2] + sm.s_bias[col];
                o.y = acc[mt][nt][3] + sm.s_bias[col + 1];
                *(float2*)(Cf + (size_t)(gm0 + 8) * DIM_ + gc) = o;
            }
        }
    }
}

// Persistent QKV: 296 CTAs steal tiles t in [0,768): z=t>>8, y=(t>>3)&31, x=t&7
__global__ __launch_bounds__(128, 2) void gemm_qkv_persistent(
    const float* __restrict__ bq, const float* __restrict__ bk,
    const float* __restrict__ bv)
{
    __shared__ GemmSmem sm;
    __shared__ int s_tile;

    for (;;) {
        if (threadIdx.x == 0) s_tile = atomicAdd(&g_ctr_qkv, 1);
        __syncthreads();
        const int t = s_tile;
        if (t >= QKV_TILES) break;
        const int z = t >> 8;
        const int by = (t >> 3) & 31;
        const int bx = t & 7;

        const __half* A;
        const __half* W;
        const float* bias;
        __half* Ch;
        if (z == 0)      { A = g_s1h; W = g_Wh;               bias = bq; Ch = g_Qh; }
        else if (z == 1) { A = g_s2h; W = g_Wh + 1048576;     bias = bk; Ch = g_Kh; }
        else             { A = g_s2h; W = g_Wh + 2 * 1048576; bias = bv; Ch = g_Vh; }

        gemm_tile(sm, bx, by, A, W, bias, Ch, nullptr);
        __syncthreads();   // all reads of s_tile/smem done before next steal
    }
}

// O-projection: plain grid (256 tiles < 296 slots, persistence gains nothing)
__global__ __launch_bounds__(128, 2) void gemm_oproj(
    const float* __restrict__ bo, float* __restrict__ out)
{
    __shared__ GemmSmem sm;
    gemm_tile(sm, blockIdx.x, blockIdx.y, g_AOh, g_Wh + 3 * 1048576, bo,
              nullptr, out);
}

// ===========================================================================
// Fused attention tile body (round-13 math, bit-identical):
// one (b,h) x 64-row i-tile; double-buffered K/V, 1 barrier/chunk.
// ===========================================================================
#define KST 36
#define VST 72

struct AttnSmem {
    uint32_t Ks[2][64 * KST];
    uint32_t Vw[2][32 * VST];
    float Atc2s[2][64][5];
};

__device__ __forceinline__ void attn_tile(
    AttnSmem& sm, int bh, int xi,
    const float* __restrict__ atc1, const float* __restrict__ atc2,
    const float* __restrict__ U, const float* __restrict__ mixp)
{
    const int b  = bh >> 4;
    const int h  = bh & 15;
    const int i0 = xi * 64;

    const int tid  = threadIdx.x;
    const int wid  = tid >> 5;
    const int lane = tid & 31;
    const int g    = lane >> 2;
    const int tg   = lane & 3;
    const int wrow = wid * 16;

    int rK[4], cK[4];
#pragma unroll
    for (int t = 0; t < 4; t++) {
        const int s = tid + t * 128;
        rK[t] = s >> 3;
        cK[t] = s & 7;
    }
    int jV[2], dV[2];
#pragma unroll
    for (int t = 0; t < 2; t++) {
        const int s = tid + t * 128;
        jV[t] = s >> 3;
        dV[t] = s & 7;
    }

    uint32_t qf[4][4];
    {
        const uint32_t* Qb = (const uint32_t*)(g_Qh + (size_t)(b * L_ + i0 + wrow) * DIM_ + h * HD_);
#pragma unroll
        for (int kb = 0; kb < 4; kb++) {
            qf[kb][0] = Qb[(size_t)g       * (DIM_ / 2) + 8 * kb + tg];
            qf[kb][1] = Qb[(size_t)(g + 8) * (DIM_ / 2) + 8 * kb + tg];
            qf[kb][2] = Qb[(size_t)g       * (DIM_ / 2) + 8 * kb + tg + 4];
            qf[kb][3] = Qb[(size_t)(g + 8) * (DIM_ / 2) + 8 * kb + tg + 4];
        }
    }

    float a1u0[5], a1u8[5];
    {
        const float* a1p = atc1 + (size_t)(b * L_ + i0 + wrow + g) * 5;
        float a1_0[5], a1_8[5];
#pragma unroll
        for (int p = 0; p < 5; p++) {
            a1_0[p] = __ldg(a1p + p);
            a1_8[p] = __ldg(a1p + 40 + p);
        }
#pragma unroll
        for (int q = 0; q < 5; q++) {
            float s0 = 0.f, s8 = 0.f;
#pragma unroll
            for (int p = 0; p < 5; p++) {
                float u = __ldg(&U[h * 25 + p * 5 + q]);
                s0 = fmaf(a1_0[p], u, s0);
                s8 = fmaf(a1_8[p], u, s8);
            }
            a1u0[q] = s0;
            a1u8[q] = s8;
        }
    }

    float m1[2] = {-1e30f, -1e30f}, l1[2] = {0.f, 0.f};
    float m2[2] = {-1e30f, -1e30f}, l2[2] = {0.f, 0.f};
    float O1[8][4], O2[8][4];
#pragma unroll
    for (int nb = 0; nb < 8; nb++)
#pragma unroll
        for (int e = 0; e < 4; e++) { O1[nb][e] = 0.f; O2[nb][e] = 0.f; }

    for (int ch = 0; ch < 8; ch++) {
        const int j0 = ch * 64;
        const int st = ch & 1;

        uint4 kq[4];
#pragma unroll
        for (int t = 0; t < 4; t++)
            kq[t] = *(const uint4*)(g_Kh + (size_t)(b * L_ + j0 + rK[t]) * DIM_ + h * HD_ + cK[t] * 8);
        uint4 ve[2], vo[2];
#pragma unroll
        for (int t = 0; t < 2; t++) {
            ve[t] = *(const uint4*)(g_Vh + (size_t)(b * L_ + j0 + 2 * jV[t])     * DIM_ + h * HD_ + dV[t] * 8);
            vo[t] = *(const uint4*)(g_Vh + (size_t)(b * L_ + j0 + 2 * jV[t] + 1) * DIM_ + h * HD_ + dV[t] * 8);
        }
        float a2reg[5];
        if (tid < 64) {
#pragma unroll
            for (int q = 0; q < 5; q++)
                a2reg[q] = __ldg(&atc2[(size_t)(b * L_ + j0 + tid) * 5 + q]);
        }

#pragma unroll
        for (int t = 0; t < 4; t++)
            *(uint4*)&sm.Ks[st][rK[t] * KST + cK[t] * 4] = kq[t];
#pragma unroll
        for (int t = 0; t < 2; t++) {
            uint4 o0, o1;
            o0.x = __byte_perm(ve[t].x, vo[t].x, 0x5410);
            o0.y = __byte_perm(ve[t].x, vo[t].x, 0x7632);
            o0.z = __byte_perm(ve[t].y, vo[t].y, 0x5410);
            o0.w = __byte_perm(ve[t].y, vo[t].y, 0x7632);
            o1.x = __byte_perm(ve[t].z, vo[t].z, 0x5410);
            o1.y = __byte_perm(ve[t].z, vo[t].z, 0x7632);
            o1.z = __byte_perm(ve[t].w, vo[t].w, 0x5410);
            o1.w = __byte_perm(ve[t].w, vo[t].w, 0x7632);
            *(uint4*)&sm.Vw[st][jV[t] * VST + dV[t] * 8]     = o0;
            *(uint4*)&sm.Vw[st][jV[t] * VST + dV[t] * 8 + 4] = o1;
        }
        if (tid < 64) {
#pragma unroll
            for (int q = 0; q < 5; q++) sm.Atc2s[st][tid][q] = a2reg[q];
        }
        __syncthreads();

        float s1[8][4];
#pragma unroll
        for (int nt = 0; nt < 8; nt++)
#pragma unroll
            for (int e = 0; e < 4; e++) s1[nt][e] = 0.f;
#pragma unroll
        for (int kb = 0; kb < 4; kb++) {
#pragma unroll
            for (int nt = 0; nt < 8; nt++) {
                uint32_t b0 = sm.Ks[st][(nt * 8 + g) * KST + 8 * kb + tg];
                uint32_t b1 = sm.Ks[st][(nt * 8 + g) * KST + 8 * kb + tg + 4];
                mma_f16(s1[nt][0], s1[nt][1], s1[nt][2], s1[nt][3],
                        qf[kb][0], qf[kb][1], qf[kb][2], qf[kb][3], b0, b1);
            }
        }

        float s2[8][4];
#pragma unroll
        for (int nt = 0; nt < 8; nt++) {
            const int c0 = nt * 8 + 2 * tg;
            float d00 = 0.f, d01 = 0.f, d80 = 0.f, d81 = 0.f;
#pragma unroll
            for (int q = 0; q < 5; q++) {
                float a20 = sm.Atc2s[st][c0][q];
                float a21 = sm.Atc2s[st][c0 + 1][q];
                d00 = fmaf(a1u0[q], a20, d00);
                d01 = fmaf(a1u0[q], a21, d01);
                d80 = fmaf(a1u8[q], a20, d80);
                d81 = fmaf(a1u8[q], a21, d81);
            }
            s2[nt][0] = d00; s2[nt][1] = d01; s2[nt][2] = d80; s2[nt][3] = d81;
#pragma unroll
            for (int e = 0; e < 4; e++) s1[nt][e] *= 0.125f;
        }

        float cm1g = -1e30f, cm1h = -1e30f, cm2g = -1e30f, cm2h = -1e30f;
#pragma unroll
        for (int nt = 0; nt < 8; nt++) {
            cm1g = fmaxf(cm1g, fmaxf(s1[nt][0], s1[nt][1]));
            cm1h = fmaxf(cm1h, fmaxf(s1[nt][2], s1[nt][3]));
            cm2g = fmaxf(cm2g, fmaxf(s2[nt][0], s2[nt][1]));
            cm2h = fmaxf(cm2h, fmaxf(s2[nt][2], s2[nt][3]));
        }
#pragma unroll
        for (int o = 1; o <= 2; o <<= 1) {
            cm1g = fmaxf(cm1g, __shfl_xor_sync(0xffffffffu, cm1g, o));
            cm1h = fmaxf(cm1h, __shfl_xor_sync(0xffffffffu, cm1h, o));
            cm2g = fmaxf(cm2g, __shfl_xor_sync(0xffffffffu, cm2g, o));
            cm2h = fmaxf(cm2h, __shfl_xor_sync(0xffffffffu, cm2h, o));
        }

        float nm, al;
        nm = fmaxf(m1[0], cm1g); al = __expf(m1[0] - nm); m1[0] = nm; l1[0] *= al;
#pragma unroll
        for (int nb = 0; nb < 8; nb++) { O1[nb][0] *= al; O1[nb][1] *= al; }
        nm = fmaxf(m1[1], cm1h); al = __expf(m1[1] - nm); m1[1] = nm; l1[1] *= al;
#pragma unroll
        for (int nb = 0; nb < 8; nb++) { O1[nb][2] *= al; O1[nb][3] *= al; }
        nm = fmaxf(m2[0], cm2g); al = __expf(m2[0] - nm); m2[0] = nm; l2[0] *= al;
#pragma unroll
        for (int nb = 0; nb < 8; nb++) { O2[nb][0] *= al; O2[nb][1] *= al; }
        nm = fmaxf(m2[1], cm2h); al = __expf(m2[1] - nm); m2[1] = nm; l2[1] *= al;
#pragma unroll
        for (int nb = 0; nb < 8; nb++) { O2[nb][2] *= al; O2[nb][3] *= al; }

        float rs1g = 0.f, rs1h = 0.f, rs2g = 0.f, rs2h = 0.f;
#pragma unroll
        for (int nt = 0; nt < 8; nt++) {
            s1[nt][0] = __expf(s1[nt][0] - m1[0]); rs1g += s1[nt][0];
            s1[nt][1] = __expf(s1[nt][1] - m1[0]); rs1g += s1[nt][1];
            s1[nt][2] = __expf(s1[nt][2] - m1[1]); rs1h += s1[nt][2];
            s1[nt][3] = __expf(s1[nt][3] - m1[1]); rs1h += s1[nt][3];
            s2[nt][0] = __expf(s2[nt][0] - m2[0]); rs2g += s2[nt][0];
            s2[nt][1] = __expf(s2[nt][1] - m2[0]); rs2g += s2[nt][1];
            s2[nt][2] = __expf(s2[nt][2] - m2[1]); rs2h += s2[nt][2];
            s2[nt][3] = __expf(s2[nt][3] - m2[1]); rs2h += s2[nt][3];
        }
#pragma unroll
        for (int o = 1; o <= 2; o <<= 1) {
            rs1g += __shfl_xor_sync(0xffffffffu, rs1g, o);
            rs1h += __shfl_xor_sync(0xffffffffu, rs1h, o);
            rs2g += __shfl_xor_sync(0xffffffffu, rs2g, o);
            rs2h += __shfl_xor_sync(0xffffffffu, rs2h, o);
        }
        l1[0] += rs1g; l1[1] += rs1h;
        l2[0] += rs2g; l2[1] += rs2h;

#pragma unroll
        for (int kb = 0; kb < 4; kb++) {
            uint32_t A1_0 = pk(s1[2 * kb][0],     s1[2 * kb][1]);
            uint32_t A1_1 = pk(s1[2 * kb][2],     s1[2 * kb][3]);
            uint32_t A1_2 = pk(s1[2 * kb + 1][0], s1[2 * kb + 1][1]);
            uint32_t A1_3 = pk(s1[2 * kb + 1][2], s1[2 * kb + 1][3]);
            uint32_t A2_0 = pk(s2[2 * kb][0],     s2[2 * kb][1]);
            uint32_t A2_1 = pk(s2[2 * kb][2],     s2[2 * kb][3]);
            uint32_t A2_2 = pk(s2[2 * kb + 1][0], s2[2 * kb + 1][1]);
            uint32_t A2_3 = pk(s2[2 * kb + 1][2], s2[2 * kb + 1][3]);

#pragma unroll
            for (int nb = 0; nb < 8; nb++) {
                uint32_t b0 = sm.Vw[st][(8 * kb + tg)     * VST + nb * 8 + g];
                uint32_t b1 = sm.Vw[st][(8 * kb + tg + 4) * VST + nb * 8 + g];
                mma_f16(O1[nb][0], O1[nb][1], O1[nb][2], O1[nb][3],
                        A1_0, A1_1, A1_2, A1_3, b0, b1);
                mma_f16(O2[nb][0], O2[nb][1], O2[nb][2], O2[nb][3],
                        A2_0, A2_1, A2_2, A2_3, b0, b1);
            }
        }
    }

    const float mixr = (tanhf(__ldg(mixp)) + 1.f) * 0.5f;
    const float w1g = (1.f - mixr) / l1[0], w1h = (1.f - mixr) / l1[1];
    const float w2g = mixr / l2[0],         w2h = mixr / l2[1];
    __half* Ao = g_AOh + (size_t)(b * L_ + i0 + wrow) * DIM_ + h * HD_;
#pragma unroll
    for (int nb = 0; nb < 8; nb++) {
        const int col = nb * 8 + 2 * tg;
        *(uint32_t*)(Ao + (size_t)g * DIM_ + col) =
            pk(O1[nb][0] * w1g + O2[nb][0] * w2g,
               O1[nb][1] * w1g + O2[nb][1] * w2g);
        *(uint32_t*)(Ao + (size_t)(g + 8) * DIM_ + col) =
            pk(O1[nb][2] * w1h + O2[nb][2] * w2h,
               O1[nb][3] * w1h + O2[nb][3] * w2h);
    }
}

// Persistent attention: 296 CTAs steal tiles t in [0,1024): bh=t>>3, xi=t&7
__global__ __launch_bounds__(128, 2) void attn_persistent(
    const float* __restrict__ atc1, const float* __restrict__ atc2,
    const float* __restrict__ U, const float* __restrict__ mixp)
{
    __shared__ AttnSmem sm;
    __shared__ int s_tile;

    for (;;) {
        if (threadIdx.x == 0) s_tile = atomicAdd(&g_ctr_attn, 1);
        __syncthreads();
        const int t = s_tile;
        if (t >= ATTN_TILES) break;
        attn_tile(sm, t >> 3, t & 7, atc1, atc2, U, mixp);
        __syncthreads();   // tile done before next steal overwrites s_tile/smem
    }
}

// ---------------------------------------------------------------------------
extern "C" void kernel_launch(void* const* d_in, const int* in_sizes, int n_in,
                              void* d_out, int out_size)
{
    const float* seq1 = (const float*)d_in[0];
    const float* seq2 = (const float*)d_in[1];
    const float* atc1 = (const float*)d_in[2];
    const float* atc2 = (const float*)d_in[3];
    const float* Wq   = (const float*)d_in[4];
    const float* bq   = (const float*)d_in[5];
    const float* Wk   = (const float*)d_in[6];
    const float* bk   = (const float*)d_in[7];
    const float* Wv   = (const float*)d_in[8];
    const float* bv   = (const float*)d_in[9];
    const float* Wo   = (const float*)d_in[10];
    const float* bo   = (const float*)d_in[11];
    const float* U    = (const float*)d_in[12];
    const float* mixp = (const float*)d_in[13];
    float* out = (float*)d_out;

    // fp32 -> fp16 conversion + counter reset (replay-safe)
    cvt_f16_kernel<<<dim3(256, 1, 6), 256>>>(seq1, seq2, Wq, Wk, Wv, Wo);

    // Persistent fused Q/K/V projections (tile-stealing, no wave tail)
    gemm_qkv_persistent<<<PERSIST_CTAS, 128>>>(bq, bk, bv);

    // Persistent fused attention
    attn_persistent<<<PERSIST_CTAS, 128>>>(atc1, atc2, U, mixp);

    // Output projection -> d_out (fp32), plain grid
    gemm_oproj<<<dim3(DIM_ / 128, B_ * L_ / 128), 128>>>(bo, out);
}

// round 17
// speedup vs baseline: 1.0482x; 1.0482x over previous
#include <cuda_runtime.h>
#include <cuda_fp16.h>
#include <math.h>
#include <cstdint>

#define B_   8
#define H_   16
#define L_   512
#define DIM_ 1024
#define HD_  64
#define SEQN (B_ * L_ * DIM_)   // 4194304

// fp16 scratch (device globals: allocation-free per harness rules)
__device__ __align__(16) __half g_Wh [4 * 1024 * 1024];   // Wq,Wk,Wv,Wo
__device__ __align__(16) __half g_s1h[SEQN];
__device__ __align__(16) __half g_s2h[SEQN];
__device__ __align__(16) __half g_Qh [SEQN];
__device__ __align__(16) __half g_Kh [SEQN];
__device__ __align__(16) __half g_Vh [SEQN];
__device__ __align__(16) __half g_AOh[SEQN];

// ===========================================================================
// helpers
// ===========================================================================
__device__ __forceinline__ uint32_t pk(float lo, float hi) {
    uint32_t d;
    asm("cvt.rn.f16x2.f32 %0, %1, %2;" : "=r"(d) : "f"(hi), "f"(lo));
    return d;
}

__device__ __forceinline__ void mma_f16(
    float& d0, float& d1, float& d2, float& d3,
    uint32_t a0, uint32_t a1, uint32_t a2, uint32_t a3,
    uint32_t b0, uint32_t b1)
{
    asm volatile(
        "mma.sync.aligned.m16n8k16.row.col.f32.f16.f16.f32 "
        "{%0,%1,%2,%3}, {%4,%5,%6,%7}, {%8,%9}, {%0,%1,%2,%3};"
        : "+f"(d0), "+f"(d1), "+f"(d2), "+f"(d3)
        : "r"(a0), "r"(a1), "r"(a2), "r"(a3), "r"(b0), "r"(b1));
}

// ===========================================================================
// One-time fp32 -> fp16 conversion of inputs (z selects tensor)
// ===========================================================================
__global__ __launch_bounds__(256) void cvt_f16_kernel(
    const float* __restrict__ s1, const float* __restrict__ s2,
    const float* __restrict__ wq, const float* __restrict__ wk,
    const float* __restrict__ wv, const float* __restrict__ wo)
{
    const int z = blockIdx.z;
    const float* src;
    __half* dst;
    int n4;
    if      (z == 0) { src = s1; dst = g_s1h;               n4 = SEQN / 4; }
    else if (z == 1) { src = s2; dst = g_s2h;               n4 = SEQN / 4; }
    else if (z == 2) { src = wq; dst = g_Wh;                n4 = 262144; }
    else if (z == 3) { src = wk; dst = g_Wh + 1048576;      n4 = 262144; }
    else if (z == 4) { src = wv; dst = g_Wh + 2 * 1048576;  n4 = 262144; }
    else             { src = wo; dst = g_Wh + 3 * 1048576;  n4 = 262144; }

    for (int i = blockIdx.x * blockDim.x + threadIdx.x; i < n4;
         i += gridDim.x * blockDim.x) {
        float4 v = __ldg((const float4*)src + i);
        uint2 o;
        o.x = pk(v.x, v.y);
        o.y = pk(v.z, v.w);
        *((uint2*)dst + i) = o;
    }
}

// ===========================================================================
// fp16-native GEMM (round-10/13 version, known-best):
// C[M,1024] = A[M,1024] @ W[1024,1024]^T + bias
// CTA tile 128x128, 4 warps (2m x 2n), warp tile 64x64. KB=32, 2-stage.
// mode 0: fused QKV (z selects, fp16 out), mode 1: O-proj (fp32 out)
// ===========================================================================
#define GK    1024
#define KB    32
#define NCH   (GK / KB)   // 32
#define SST   20

__global__ __launch_bounds__(128, 2) void gemm_f16(
    const float* __restrict__ bq, const float* __restrict__ bk,
    const float* __restrict__ bv, float* __restrict__ C_ext, int mode)
{
    const __half* A;
    const __half* W;
    const float* bias;
    __half* Ch = nullptr;
    float* Cf = nullptr;
    if (mode == 1) {
        A = g_AOh; W = g_Wh + 3 * 1048576; bias = bq; Cf = C_ext;
    } else {
        const int z = blockIdx.z;
        if (z == 0)      { A = g_s1h; W = g_Wh;               bias = bq; Ch = g_Qh; }
        else if (z == 1) { A = g_s2h; W = g_Wh + 1048576;     bias = bk; Ch = g_Kh; }
        else             { A = g_s2h; W = g_Wh + 2 * 1048576; bias = bv; Ch = g_Vh; }
    }

    __shared__ uint32_t As[2][128 * SST];
    __shared__ uint32_t Bs[2][128 * SST];
    __shared__ float s_bias[128];

    const int tid  = threadIdx.x;
    const int wid  = tid >> 5;
    const int lane = tid & 31;
    const int g    = lane >> 2;
    const int tg   = lane & 3;
    const int mrow = (wid >> 1) * 64;
    const int ncol = (wid & 1) * 64;

    const __half* Arow = A + (size_t)blockIdx.y * 128 * GK;
    const __half* Wrow = W + (size_t)blockIdx.x * 128 * GK;

    if (tid < 128) s_bias[tid] = bias[blockIdx.x * 128 + tid];

    int rL[4], qL[4];
#pragma unroll
    for (int t = 0; t < 4; t++) {
        const int s = tid + t * 128;
        rL[t] = s >> 2;
        qL[t] = s & 3;
    }

    float acc[4][8][4];
#pragma unroll
    for (int mt = 0; mt < 4; mt++)
#pragma unroll
        for (int nt = 0; nt < 8; nt++)
#pragma unroll
            for (int e = 0; e < 4; e++) acc[mt][nt][e] = 0.f;

#pragma unroll
    for (int t = 0; t < 4; t++) {
        uint4 a = *(const uint4*)(Arow + (size_t)rL[t] * GK + qL[t] * 8);
        uint4 b = *(const uint4*)(Wrow + (size_t)rL[t] * GK + qL[t] * 8);
        *(uint4*)&As[0][rL[t] * SST + qL[t] * 4] = a;
        *(uint4*)&Bs[0][rL[t] * SST + qL[t] * 4] = b;
    }
    __syncthreads();

    for (int i = 0; i < NCH; i++) {
        const int st = i & 1;
        uint4 va[4], vb[4];
        const bool more = (i + 1 < NCH);
        if (more) {
            const int ko = (i + 1) * KB;
#pragma unroll
            for (int t = 0; t < 4; t++) {
                va[t] = *(const uint4*)(Arow + (size_t)rL[t] * GK + ko + qL[t] * 8);
                vb[t] = *(const uint4*)(Wrow + (size_t)rL[t] * GK + ko + qL[t] * 8);
            }
        }

#pragma unroll
        for (int ks = 0; ks < 2; ks++) {
            uint32_t a[4][4];
#pragma unroll
            for (int mt = 0; mt < 4; mt++) {
                const int rb = mrow + mt * 16 + g;
                a[mt][0] = As[st][(rb)     * SST + ks * 8 + tg];
                a[mt][1] = As[st][(rb + 8) * SST + ks * 8 + tg];
                a[mt][2] = As[st][(rb)     * SST + ks * 8 + tg + 4];
                a[mt][3] = As[st][(rb + 8) * SST + ks * 8 + tg + 4];
            }
#pragma unroll
            for (int nt = 0; nt < 8; nt++) {
                const int rw = ncol + nt * 8 + g;
                uint32_t b0 = Bs[st][rw * SST + ks * 8 + tg];
                uint32_t b1 = Bs[st][rw * SST + ks * 8 + tg + 4];
#pragma unroll
                for (int mt = 0; mt < 4; mt++)
                    mma_f16(acc[mt][nt][0], acc[mt][nt][1], acc[mt][nt][2], acc[mt][nt][3],
                            a[mt][0], a[mt][1], a[mt][2], a[mt][3], b0, b1);
            }
        }

        if (more) {
            const int ns = st ^ 1;
#pragma unroll
            for (int t = 0; t < 4; t++) {
                *(uint4*)&As[ns][rL[t] * SST + qL[t] * 4] = va[t];
                *(uint4*)&Bs[ns][rL[t] * SST + qL[t] * 4] = vb[t];
            }
            __syncthreads();
        }
    }

    if (mode == 1) {
#pragma unroll
        for (int mt = 0; mt < 4; mt++) {
#pragma unroll
            for (int nt = 0; nt < 8; nt++) {
                const int row = mrow + mt * 16 + g;
                const int col = ncol + nt * 8 + 2 * tg;
                const int gm0 = blockIdx.y * 128 + row;
                const int gc  = blockIdx.x * 128 + col;
                float2 o;
                o.x = acc[mt][nt][0] + s_bias[col];
                o.y = acc[mt][nt][1] + s_bias[col + 1];
                *(float2*)(Cf + (size_t)gm0 * DIM_ + gc) = o;
                o.x = acc[mt][nt][2] + s_bias[col];
                o.y = acc[mt][nt][3] + s_bias[col + 1];
                *(float2*)(Cf + (size_t)(gm0 + 8) * DIM_ + gc) = o;
            }
        }
    } else {
#pragma unroll
        for (int mt = 0; mt < 4; mt++) {
#pragma unroll
            for (int nt = 0; nt < 8; nt++) {
                const int row = mrow + mt * 16 + g;
                const int col = ncol + nt * 8 + 2 * tg;
                const int gm0 = blockIdx.y * 128 + row;
                const int gc  = blockIdx.x * 128 + col;
                *(uint32_t*)(Ch + (size_t)gm0 * DIM_ + gc) =
                    pk(acc[mt][nt][0] + s_bias[col], acc[mt][nt][1] + s_bias[col + 1]);
                *(uint32_t*)(Ch + (size_t)(gm0 + 8) * DIM_ + gc) =
                    pk(acc[mt][nt][2] + s_bias[col], acc[mt][nt][3] + s_bias[col + 1]);
            }
        }
    }
}

// ===========================================================================
// Fused attention (round-13 version, known-best):
// double-buffered K/V SMEM, ONE barrier per chunk.
// ===========================================================================
#define KST 36
#define VST 72

__global__ __launch_bounds__(128) void attn_fused_kernel(
    const float* __restrict__ atc1, const float* __restrict__ atc2,
    const float* __restrict__ U, const float* __restrict__ mixp)
{
    const int bh = blockIdx.y;
    const int b  = bh >> 4;
    const int h  = bh & 15;
    const int i0 = blockIdx.x * 64;

    __shared__ uint32_t Ks[2][64 * KST];
    __shared__ uint32_t Vw[2][32 * VST];
    __shared__ float Atc2s[2][64][5];

    const int tid  = threadIdx.x;
    const int wid  = tid >> 5;
    const int lane = tid & 31;
    const int g    = lane >> 2;
    const int tg   = lane & 3;
    const int wrow = wid * 16;

    int rK[4], cK[4];
#pragma unroll
    for (int t = 0; t < 4; t++) {
        const int s = tid + t * 128;
        rK[t] = s >> 3;
        cK[t] = s & 7;
    }
    int jV[2], dV[2];
#pragma unroll
    for (int t = 0; t < 2; t++) {
        const int s = tid + t * 128;
        jV[t] = s >> 3;
        dV[t] = s & 7;
    }

    uint32_t qf[4][4];
    {
        const uint32_t* Qb = (const uint32_t*)(g_Qh + (size_t)(b * L_ + i0 + wrow) * DIM_ + h * HD_);
#pragma unroll
        for (int kb = 0; kb < 4; kb++) {
            qf[kb][0] = Qb[(size_t)g       * (DIM_ / 2) + 8 * kb + tg];
            qf[kb][1] = Qb[(size_t)(g + 8) * (DIM_ / 2) + 8 * kb + tg];
            qf[kb][2] = Qb[(size_t)g       * (DIM_ / 2) + 8 * kb + tg + 4];
            qf[kb][3] = Qb[(size_t)(g + 8) * (DIM_ / 2) + 8 * kb + tg + 4];
        }
    }

    float a1u0[5], a1u8[5];
    {
        const float* a1p = atc1 + (size_t)(b * L_ + i0 + wrow + g) * 5;
        float a1_0[5], a1_8[5];
#pragma unroll
        for (int p = 0; p < 5; p++) {
            a1_0[p] = __ldg(a1p + p);
            a1_8[p] = __ldg(a1p + 40 + p);
        }
#pragma unroll
        for (int q = 0; q < 5; q++) {
            float s0 = 0.f, s8 = 0.f;
#pragma unroll
            for (int p = 0; p < 5; p++) {
                float u = __ldg(&U[h * 25 + p * 5 + q]);
                s0 = fmaf(a1_0[p], u, s0);
                s8 = fmaf(a1_8[p], u, s8);
            }
            a1u0[q] = s0;
            a1u8[q] = s8;
        }
    }

    float m1[2] = {-1e30f, -1e30f}, l1[2] = {0.f, 0.f};
    float m2[2] = {-1e30f, -1e30f}, l2[2] = {0.f, 0.f};
    float O1[8][4], O2[8][4];
#pragma unroll
    for (int nb = 0; nb < 8; nb++)
#pragma unroll
        for (int e = 0; e < 4; e++) { O1[nb][e] = 0.f; O2[nb][e] = 0.f; }

    for (int ch = 0; ch < 8; ch++) {
        const int j0 = ch * 64;
        const int st = ch & 1;

        uint4 kq[4];
#pragma unroll
        for (int t = 0; t < 4; t++)
            kq[t] = *(const uint4*)(g_Kh + (size_t)(b * L_ + j0 + rK[t]) * DIM_ + h * HD_ + cK[t] * 8);
        uint4 ve[2], vo[2];
#pragma unroll
        for (int t = 0; t < 2; t++) {
            ve[t] = *(const uint4*)(g_Vh + (size_t)(b * L_ + j0 + 2 * jV[t])     * DIM_ + h * HD_ + dV[t] * 8);
            vo[t] = *(const uint4*)(g_Vh + (size_t)(b * L_ + j0 + 2 * jV[t] + 1) * DIM_ + h * HD_ + dV[t] * 8);
        }
        float a2reg[5];
        if (tid < 64) {
#pragma unroll
            for (int q = 0; q < 5; q++)
                a2reg[q] = __ldg(&atc2[(size_t)(b * L_ + j0 + tid) * 5 + q]);
        }

#pragma unroll
        for (int t = 0; t < 4; t++)
            *(uint4*)&Ks[st][rK[t] * KST + cK[t] * 4] = kq[t];
#pragma unroll
        for (int t = 0; t < 2; t++) {
            uint4 o0, o1;
            o0.x = __byte_perm(ve[t].x, vo[t].x, 0x5410);
            o0.y = __byte_perm(ve[t].x, vo[t].x, 0x7632);
            o0.z = __byte_perm(ve[t].y, vo[t].y, 0x5410);
            o0.w = __byte_perm(ve[t].y, vo[t].y, 0x7632);
            o1.x = __byte_perm(ve[t].z, vo[t].z, 0x5410);
            o1.y = __byte_perm(ve[t].z, vo[t].z, 0x7632);
            o1.z = __byte_perm(ve[t].w, vo[t].w, 0x5410);
            o1.w = __byte_perm(ve[t].w, vo[t].w, 0x7632);
            *(uint4*)&Vw[st][jV[t] * VST + dV[t] * 8]     = o0;
            *(uint4*)&Vw[st][jV[t] * VST + dV[t] * 8 + 4] = o1;
        }
        if (tid < 64) {
#pragma unroll
            for (int q = 0; q < 5; q++) Atc2s[st][tid][q] = a2reg[q];
        }
        __syncthreads();

        float s1[8][4];
#pragma unroll
        for (int nt = 0; nt < 8; nt++)
#pragma unroll
            for (int e = 0; e < 4; e++) s1[nt][e] = 0.f;
#pragma unroll
        for (int kb = 0; kb < 4; kb++) {
#pragma unroll
            for (int nt = 0; nt < 8; nt++) {
                uint32_t b0 = Ks[st][(nt * 8 + g) * KST + 8 * kb + tg];
                uint32_t b1 = Ks[st][(nt * 8 + g) * KST + 8 * kb + tg + 4];
                mma_f16(s1[nt][0], s1[nt][1], s1[nt][2], s1[nt][3],
                        qf[kb][0], qf[kb][1], qf[kb][2], qf[kb][3], b0, b1);
            }
        }

        float s2[8][4];
#pragma unroll
        for (int nt = 0; nt < 8; nt++) {
            const int c0 = nt * 8 + 2 * tg;
            float d00 = 0.f, d01 = 0.f, d80 = 0.f, d81 = 0.f;
#pragma unroll
            for (int q = 0; q < 5; q++) {
                float a20 = Atc2s[st][c0][q];
                float a21 = Atc2s[st][c0 + 1][q];
                d00 = fmaf(a1u0[q], a20, d00);
                d01 = fmaf(a1u0[q], a21, d01);
                d80 = fmaf(a1u8[q], a20, d80);
                d81 = fmaf(a1u8[q], a21, d81);
            }
            s2[nt][0] = d00; s2[nt][1] = d01; s2[nt][2] = d80; s2[nt][3] = d81;
#pragma unroll
            for (int e = 0; e < 4; e++) s1[nt][e] *= 0.125f;
        }

        float cm1g = -1e30f, cm1h = -1e30f, cm2g = -1e30f, cm2h = -1e30f;
#pragma unroll
        for (int nt = 0; nt < 8; nt++) {
            cm1g = fmaxf(cm1g, fmaxf(s1[nt][0], s1[nt][1]));
            cm1h = fmaxf(cm1h, fmaxf(s1[nt][2], s1[nt][3]));
            cm2g = fmaxf(cm2g, fmaxf(s2[nt][0], s2[nt][1]));
            cm2h = fmaxf(cm2h, fmaxf(s2[nt][2], s2[nt][3]));
        }
#pragma unroll
        for (int o = 1; o <= 2; o <<= 1) {
            cm1g = fmaxf(cm1g, __shfl_xor_sync(0xffffffffu, cm1g, o));
            cm1h = fmaxf(cm1h, __shfl_xor_sync(0xffffffffu, cm1h, o));
            cm2g = fmaxf(cm2g, __shfl_xor_sync(0xffffffffu, cm2g, o));
            cm2h = fmaxf(cm2h, __shfl_xor_sync(0xffffffffu, cm2h, o));
        }

        float nm, al;
        nm = fmaxf(m1[0], cm1g); al = __expf(m1[0] - nm); m1[0] = nm; l1[0] *= al;
#pragma unroll
        for (int nb = 0; nb < 8; nb++) { O1[nb][0] *= al; O1[nb][1] *= al; }
        nm = fmaxf(m1[1], cm1h); al = __expf(m1[1] - nm); m1[1] = nm; l1[1] *= al;
#pragma unroll
        for (int nb = 0; nb < 8; nb++) { O1[nb][2] *= al; O1[nb][3] *= al; }
        nm = fmaxf(m2[0], cm2g); al = __expf(m2[0] - nm); m2[0] = nm; l2[0] *= al;
#pragma unroll
        for (int nb = 0; nb < 8; nb++) { O2[nb][0] *= al; O2[nb][1] *= al; }
        nm = fmaxf(m2[1], cm2h); al = __expf(m2[1] - nm); m2[1] = nm; l2[1] *= al;
#pragma unroll
        for (int nb = 0; nb < 8; nb++) { O2[nb][2] *= al; O2[nb][3] *= al; }

        float rs1g = 0.f, rs1h = 0.f, rs2g = 0.f, rs2h = 0.f;
#pragma unroll
        for (int nt = 0; nt < 8; nt++) {
            s1[nt][0] = __expf(s1[nt][0] - m1[0]); rs1g += s1[nt][0];
            s1[nt][1] = __expf(s1[nt][1] - m1[0]); rs1g += s1[nt][1];
            s1[nt][2] = __expf(s1[nt][2] - m1[1]); rs1h += s1[nt][2];
            s1[nt][3] = __expf(s1[nt][3] - m1[1]); rs1h += s1[nt][3];
            s2[nt][0] = __expf(s2[nt][0] - m2[0]); rs2g += s2[nt][0];
            s2[nt][1] = __expf(s2[nt][1] - m2[0]); rs2g += s2[nt][1];
            s2[nt][2] = __expf(s2[nt][2] - m2[1]); rs2h += s2[nt][2];
            s2[nt][3] = __expf(s2[nt][3] - m2[1]); rs2h += s2[nt][3];
        }
#pragma unroll
        for (int o = 1; o <= 2; o <<= 1) {
            rs1g += __shfl_xor_sync(0xffffffffu, rs1g, o);
            rs1h += __shfl_xor_sync(0xffffffffu, rs1h, o);
            rs2g += __shfl_xor_sync(0xffffffffu, rs2g, o);
            rs2h += __shfl_xor_sync(0xffffffffu, rs2h, o);
        }
        l1[0] += rs1g; l1[1] += rs1h;
        l2[0] += rs2g; l2[1] += rs2h;

#pragma unroll
        for (int kb = 0; kb < 4; kb++) {
            uint32_t A1_0 = pk(s1[2 * kb][0],     s1[2 * kb][1]);
            uint32_t A1_1 = pk(s1[2 * kb][2],     s1[2 * kb][3]);
            uint32_t A1_2 = pk(s1[2 * kb + 1][0], s1[2 * kb + 1][1]);
            uint32_t A1_3 = pk(s1[2 * kb + 1][2], s1[2 * kb + 1][3]);
            uint32_t A2_0 = pk(s2[2 * kb][0],     s2[2 * kb][1]);
            uint32_t A2_1 = pk(s2[2 * kb][2],     s2[2 * kb][3]);
            uint32_t A2_2 = pk(s2[2 * kb + 1][0], s2[2 * kb + 1][1]);
            uint32_t A2_3 = pk(s2[2 * kb + 1][2], s2[2 * kb + 1][3]);

#pragma unroll
            for (int nb = 0; nb < 8; nb++) {
                uint32_t b0 = Vw[st][(8 * kb + tg)     * VST + nb * 8 + g];
                uint32_t b1 = Vw[st][(8 * kb + tg + 4) * VST + nb * 8 + g];
                mma_f16(O1[nb][0], O1[nb][1], O1[nb][2], O1[nb][3],
                        A1_0, A1_1, A1_2, A1_3, b0, b1);
                mma_f16(O2[nb][0], O2[nb][1], O2[nb][2], O2[nb][3],
                        A2_0, A2_1, A2_2, A2_3, b0, b1);
            }
        }
    }

    const float mixr = (tanhf(__ldg(mixp)) + 1.f) * 0.5f;
    const float w1g = (1.f - mixr) / l1[0], w1h = (1.f - mixr) / l1[1];
    const float w2g = mixr / l2[0],         w2h = mixr / l2[1];
    __half* Ao = g_AOh + (size_t)(b * L_ + i0 + wrow) * DIM_ + h * HD_;
#pragma unroll
    for (int nb = 0; nb < 8; nb++) {
        const int col = nb * 8 + 2 * tg;
        *(uint32_t*)(Ao + (size_t)g * DIM_ + col) =
            pk(O1[nb][0] * w1g + O2[nb][0] * w2g,
               O1[nb][1] * w1g + O2[nb][1] * w2g);
        *(uint32_t*)(Ao + (size_t)(g + 8) * DIM_ + col) =
            pk(O1[nb][2] * w1h + O2[nb][2] * w2h,
               O1[nb][3] * w1h + O2[nb][3] * w2h);
    }
}

// ---------------------------------------------------------------------------
extern "C" void kernel_launch(void* const* d_in, const int* in_sizes, int n_in,
                              void* d_out, int out_size)
{
    const float* seq1 = (const float*)d_in[0];
    const float* seq2 = (const float*)d_in[1];
    const float* atc1 = (const float*)d_in[2];
    const float* atc2 = (const float*)d_in[3];
    const float* Wq   = (const float*)d_in[4];
    const float* bq   = (const float*)d_in[5];
    const float* Wk   = (const float*)d_in[6];
    const float* bk   = (const float*)d_in[7];
    const float* Wv   = (const float*)d_in[8];
    const float* bv   = (const float*)d_in[9];
    const float* Wo   = (const float*)d_in[10];
    const float* bo   = (const float*)d_in[11];
    const float* U    = (const float*)d_in[12];
    const float* mixp = (const float*)d_in[13];
    float* out = (float*)d_out;

    const int M = B_ * L_;                       // 4096

    // One-time fp32 -> fp16 conversion of seq1/seq2/Wq/Wk/Wv/Wo
    cvt_f16_kernel<<<dim3(256, 1, 6), 256>>>(seq1, seq2, Wq, Wk, Wv, Wo);

    // Fused Q/K/V projections (fp16-native, KB=32)
    gemm_f16<<<dim3(DIM_ / 128, M / 128, 3), 128>>>(bq, bk, bv, nullptr, 0);

    // Fused attention (double-buffered K/V, 1 barrier/chunk)
    attn_fused_kernel<<<dim3(L_ / 64, B_ * H_), 128>>>(atc1, atc2, U, mixp);

    // Output projection -> d_out (fp32)
    gemm_f16<<<dim3(DIM_ / 128, M / 128, 1), 128>>>(bo, nullptr, nullptr, out, 1);
}